// round 1
// baseline (speedup 1.0000x reference)
#include <cuda_runtime.h>
#include <math.h>

// DistinctionLoss: features [8,4096,256] f32, scores [8,4096,1] f32 -> scalar f32.
//
// Key algebraic reduction: mean(gram) = sum_b ||s_b||^2 / (B*N^2) where
// s_b = sum_n normalize(features[b,n,:]).  No O(N^2) Gram needed.

#define BB 8
#define NN 4096
#define DD 256
#define ROWS_PER_BLOCK 64          // 8 warps x 8 rows
#define NBLOCKS ((BB * NN) / ROWS_PER_BLOCK)  // 512

// Scratch (no cudaMalloc allowed).
__device__ float  g_rnorm[BB * NN];     // 1/||row||
__device__ float  g_s[BB * DD];         // per-batch sum of unit rows
__device__ double g_bce;                // BCE numerator accumulator

__global__ void zero_kernel() {
    int t = blockIdx.x * blockDim.x + threadIdx.x;
    if (t < BB * DD) g_s[t] = 0.0f;
    if (t == 0) g_bce = 0.0;
}

// Pass 1: per-row 1/norm + accumulate s_b.
__global__ void __launch_bounds__(256) pass1_kernel(const float* __restrict__ feat) {
    __shared__ float s_acc[DD];
    int tid  = threadIdx.x;
    int wid  = tid >> 5;
    int lane = tid & 31;
    s_acc[tid] = 0.0f;
    __syncthreads();

    int blockRowBase = blockIdx.x * ROWS_PER_BLOCK;
    int b    = blockRowBase / NN;       // 64 | 4096, whole block in one batch
    int row0 = blockRowBase + wid * 8;

    float acc[8] = {0.f, 0.f, 0.f, 0.f, 0.f, 0.f, 0.f, 0.f};

    #pragma unroll
    for (int r = 0; r < 8; r++) {
        int row = row0 + r;
        const float4* p = (const float4*)(feat + (size_t)row * DD);
        float4 v0 = p[lane];
        float4 v1 = p[lane + 32];
        float ss = v0.x*v0.x + v0.y*v0.y + v0.z*v0.z + v0.w*v0.w
                 + v1.x*v1.x + v1.y*v1.y + v1.z*v1.z + v1.w*v1.w;
        #pragma unroll
        for (int o = 16; o > 0; o >>= 1)
            ss += __shfl_xor_sync(0xffffffffu, ss, o);
        // norm never near 0 for random normal data; eps guard anyway
        float rn = rsqrtf(fmaxf(ss, 1e-24f));
        if (lane == 0) g_rnorm[row] = rn;
        acc[0] += v0.x * rn; acc[1] += v0.y * rn;
        acc[2] += v0.z * rn; acc[3] += v0.w * rn;
        acc[4] += v1.x * rn; acc[5] += v1.y * rn;
        acc[6] += v1.z * rn; acc[7] += v1.w * rn;
    }

    int d0 = lane * 4;
    atomicAdd(&s_acc[d0 + 0], acc[0]);
    atomicAdd(&s_acc[d0 + 1], acc[1]);
    atomicAdd(&s_acc[d0 + 2], acc[2]);
    atomicAdd(&s_acc[d0 + 3], acc[3]);
    atomicAdd(&s_acc[128 + d0 + 0], acc[4]);
    atomicAdd(&s_acc[128 + d0 + 1], acc[5]);
    atomicAdd(&s_acc[128 + d0 + 2], acc[6]);
    atomicAdd(&s_acc[128 + d0 + 3], acc[7]);
    __syncthreads();

    atomicAdd(&g_s[b * DD + tid], s_acc[tid]);
}

// Pass 2: per-row dot with s_b -> target -> BCE term; accumulate.
__global__ void __launch_bounds__(256) pass2_kernel(const float* __restrict__ feat,
                                                    const float* __restrict__ scores) {
    __shared__ float s_vec[DD];
    __shared__ float s_red[8];
    int tid  = threadIdx.x;
    int wid  = tid >> 5;
    int lane = tid & 31;

    int blockRowBase = blockIdx.x * ROWS_PER_BLOCK;
    int b = blockRowBase / NN;
    s_vec[tid] = g_s[b * DD + tid];
    __syncthreads();

    const float4* sv = (const float4*)s_vec;
    float4 s0 = sv[lane];
    float4 s1 = sv[lane + 32];

    int row0 = blockRowBase + wid * 8;
    float local = 0.0f;

    #pragma unroll
    for (int r = 0; r < 8; r++) {
        int row = row0 + r;
        const float4* p = (const float4*)(feat + (size_t)row * DD);
        float4 v0 = p[lane];
        float4 v1 = p[lane + 32];
        float dot = v0.x*s0.x + v0.y*s0.y + v0.z*s0.z + v0.w*s0.w
                  + v1.x*s1.x + v1.y*s1.y + v1.z*s1.z + v1.w*s1.w;
        #pragma unroll
        for (int o = 16; o > 0; o >>= 1)
            dot += __shfl_xor_sync(0xffffffffu, dot, o);
        if (lane == 0) {
            float fs  = dot * g_rnorm[row];          // f . s_b
            float sim = (fs - 1.0f) * (1.0f / (float)(NN - 1));
            float t   = 1.0f - fmaxf(sim, 0.0f);
            float sc  = scores[row];
            float ls  = fmaxf(logf(sc),    -100.0f);
            float l1  = fmaxf(log1pf(-sc), -100.0f);
            local += -(t * ls + (1.0f - t) * l1);
        }
    }

    if (lane == 0) s_red[wid] = local;
    __syncthreads();
    if (tid == 0) {
        float sum = 0.0f;
        #pragma unroll
        for (int i = 0; i < 8; i++) sum += s_red[i];
        atomicAdd(&g_bce, (double)sum);
    }
}

// Finalizer: sum_b ||s_b||^2 + combine with BCE accumulator.
__global__ void final_kernel(float* __restrict__ out) {
    __shared__ float red[256];
    int tid = threadIdx.x;
    float ss = 0.0f;
    #pragma unroll
    for (int i = 0; i < (BB * DD) / 256; i++) {
        float v = g_s[tid + i * 256];
        ss += v * v;
    }
    red[tid] = ss;
    __syncthreads();
    #pragma unroll
    for (int o = 128; o > 0; o >>= 1) {
        if (tid < o) red[tid] += red[tid + o];
        __syncthreads();
    }
    if (tid == 0) {
        double bce       = g_bce / (double)(BB * NN);
        double mean_gram = (double)red[0] /
                           ((double)BB * (double)NN * (double)NN);
        out[0] = (float)(bce + (1.0 - mean_gram));
    }
}

extern "C" void kernel_launch(void* const* d_in, const int* in_sizes, int n_in,
                              void* d_out, int out_size) {
    const float* feat   = (const float*)d_in[0];
    const float* scores = (const float*)d_in[1];
    float* out = (float*)d_out;

    zero_kernel<<<8, 256>>>();
    pass1_kernel<<<NBLOCKS, 256>>>(feat);
    pass2_kernel<<<NBLOCKS, 256>>>(feat, scores);
    final_kernel<<<1, 256>>>(out);
}